// round 7
// baseline (speedup 1.0000x reference)
#include <cuda_runtime.h>

#define EC 64

__device__ __forceinline__ float ex2f(float x) {
    float y; asm("ex2.approx.ftz.f32 %0, %1;" : "=f"(y) : "f"(x)); return y;
}
__device__ __forceinline__ float rcpf(float x) {
    float y; asm("rcp.approx.ftz.f32 %0, %1;" : "=f"(y) : "f"(x)); return y;
}
// sigmoid via HW tanh: sig(x) = 0.5*tanh(0.5x) + 0.5  (1 MUFU op, abs err ~1e-5)
__device__ __forceinline__ float sigf(float x) {
    float t; asm("tanh.approx.f32 %0, %1;" : "=f"(t) : "f"(0.5f * x));
    return fmaf(0.5f, t, 0.5f);
}

// 1 pt/thread, single balanced wave (7 CTAs/SM via launch_bounds(256,7)),
// e-tile of 2 front-batched LDG.128, log2-domain pre-scaled inv_cov.
__global__ void __launch_bounds__(256, 7) rbf_fused(
    const float* __restrict__ wsp,
    const float4* __restrict__ act,
    const float* __restrict__ dists,
    const float* __restrict__ constants,
    const float* __restrict__ centers,
    const float* __restrict__ radii,
    const float* __restrict__ rotations,
    float4* __restrict__ out,
    float* __restrict__ pen_out,
    int n_pts) {
    __shared__ float4 sp[EC * 3];
    int tid = threadIdx.x;

    // ---- per-block setup: threads 0..63 build packed params in smem ----
    if (tid < EC) {
        int e = tid;
        float rx = fabsf(radii[e * 3 + 0]) + 0.005f;
        float ry = fabsf(radii[e * 3 + 1]) + 0.005f;
        float rz = fabsf(radii[e * 3 + 2]) + 0.005f;
        float d0 = 1.0f / (rx + 1e-8f);
        float d1 = 1.0f / (ry + 1e-8f);
        float d2 = 1.0f / (rz + 1e-8f);

        float a0 = rotations[e * 3 + 0];
        float a1 = rotations[e * 3 + 1];
        float a2 = rotations[e * 3 + 2];
        float cx = cosf(a0), sx = sinf(a0);
        float cy = cosf(a1), sy = sinf(a1);
        float cz = cosf(a2), sz = sinf(a2);

        float R00 = cz * cy, R01 = cz * sy * sx - sz * cx, R02 = cz * sy * cx + sz * sx;
        float R10 = sz * cy, R11 = sz * sy * sx + cz * cx, R12 = sz * sy * cx - cz * sx;
        float R20 = -sy,     R21 = cy * sx,                R22 = cy * cx;

        float c00 = d0 * R00 * R00 + d1 * R01 * R01 + d2 * R02 * R02;
        float c01 = d0 * R00 * R10 + d1 * R01 * R11 + d2 * R02 * R12;
        float c02 = d0 * R00 * R20 + d1 * R01 * R21 + d2 * R02 * R22;
        float c11 = d0 * R10 * R10 + d1 * R11 * R11 + d2 * R12 * R12;
        float c12 = d0 * R10 * R20 + d1 * R11 * R21 + d2 * R12 * R22;
        float c22 = d0 * R20 * R20 + d1 * R21 * R21 + d2 * R22 * R22;

        // Pre-scale into log2 domain: rbf = |c| * 2^(s·q-form)
        // s_diag = -0.5*log2e*c_ii ; s_offdiag = -log2e*c_ij (2x folded in)
        const float KD = -0.7213475204444817f;   // -0.5*log2(e)
        const float KO = -1.4426950408889634f;   // -log2(e)
        float s00 = KD * c00, s11 = KD * c11, s22 = KD * c22;
        float s01 = KO * c01, s02 = KO * c02, s12 = KO * c12;

        float ccx = centers[e * 3 + 0];
        float ccy = centers[e * 3 + 1];
        float ccz = centers[e * 3 + 2];
        float cab = fabsf(constants[e]);

        sp[e * 3 + 0] = make_float4(s00, s01, s02, s11);
        sp[e * 3 + 1] = make_float4(s12, s22, ccx, ccy);
        sp[e * 3 + 2] = make_float4(ccz, cab, 0.0f, 0.0f);

        // bbox penalty term, added once (pen_out pre-zeroed by memset)
        if (blockIdx.x == 0) {
            float p = fmaxf(ccx - 0.6f, 0.0f) + fmaxf(ccy - 0.6f, 0.0f) + fmaxf(ccz - 0.6f, 0.0f)
                    + fmaxf(-0.6f - ccx, 0.0f) + fmaxf(-0.6f - ccy, 0.0f) + fmaxf(-0.35f - ccz, 0.0f);
            if (p != 0.0f) atomicAdd(pen_out, p);
        }
    }
    __syncthreads();

    int n = blockIdx.x * 256 + tid;
    float pen = 0.0f;

    if (n < n_pts) {
        float x = wsp[3 * n + 0];
        float y = wsp[3 * n + 1];
        float z = wsp[3 * n + 2];
        float negl2d = -1.4426950408889634f * dists[n];

        float Ux = 0.f, Uy = 0.f, Uz = 0.f, Uw = 0.f, S = 0.f;

        for (int e = 0; e < EC; e += 2) {
            float4 A0 = act[(size_t)e * n_pts + n];
            float4 A1 = act[(size_t)(e + 1) * n_pts + n];

            #pragma unroll
            for (int j = 0; j < 2; j++) {
                float4 pa = sp[(e + j) * 3 + 0];
                float4 pb = sp[(e + j) * 3 + 1];
                float4 pc = sp[(e + j) * 3 + 2];

                float dx = x - pb.z, dy = y - pb.w, dz = z - pc.x;
                // symmetric form, already in log2 domain:
                // q = dx*(s00 dx + s01 dy + s02 dz) + dy*(s11 dy + s12 dz) + dz*(s22 dz)
                float A = fmaf(pa.z, dz, fmaf(pa.y, dy, pa.x * dx));
                float B = fmaf(pb.x, dz, pa.w * dy);
                float C = pb.y * dz;
                float q = fmaf(dz, C, fmaf(dy, B, dx * A));

                float rbf = pc.y * ex2f(q);
                pen += fmaxf(rbf - 0.01f, 0.0f);
                S += rbf;

                float4 a = (j == 0) ? A0 : A1;
                float alpha = 1.0f - ex2f(fmaxf(a.w, 0.0f) * negl2d);
                Ux += rbf * sigf(a.x);
                Uy += rbf * sigf(a.y);
                Uz += rbf * sigf(a.z);
                Uw += rbf * alpha;
            }
        }

        float inv = rcpf(S + 1e-6f);
        out[n] = make_float4(Ux * inv, Uy * inv, Uz * inv, Uw * inv);
    }

    // penalty mean-term reduction: warp shuffle -> smem -> one atomic per block
    #pragma unroll
    for (int o = 16; o; o >>= 1) pen += __shfl_down_sync(0xffffffffu, pen, o);
    __shared__ float wsum[8];
    if ((tid & 31) == 0) wsum[tid >> 5] = pen;
    __syncthreads();
    if (tid == 0) {
        float s = 0.0f;
        #pragma unroll
        for (int i = 0; i < 8; i++) s += wsum[i];
        atomicAdd(pen_out, s * (0.001f / (float)n_pts));
    }
}

extern "C" void kernel_launch(void* const* d_in, const int* in_sizes, int n_in,
                              void* d_out, int out_size) {
    const float* wsp       = (const float*)d_in[0];
    const float* act       = (const float*)d_in[1];
    const float* dists     = (const float*)d_in[2];
    const float* constants = (const float*)d_in[3];
    const float* centers   = (const float*)d_in[4];
    const float* radii     = (const float*)d_in[5];
    const float* rot       = (const float*)d_in[6];

    int n_pts = in_sizes[0] / 3;
    float* out = (float*)d_out;
    float* pen = out + (out_size - 1);

    cudaMemsetAsync(pen, 0, sizeof(float));

    int blocks = (n_pts + 255) / 256;
    rbf_fused<<<blocks, 256>>>(wsp, (const float4*)act, dists,
                               constants, centers, radii, rot,
                               (float4*)out, pen, n_pts);
}

// round 12
// speedup vs baseline: 1.2409x; 1.2409x over previous
#include <cuda_runtime.h>

#define EC 64

__device__ __forceinline__ float ex2f(float x) {
    float y; asm("ex2.approx.ftz.f32 %0, %1;" : "=f"(y) : "f"(x)); return y;
}
__device__ __forceinline__ float rcpf(float x) {
    float y; asm("rcp.approx.ftz.f32 %0, %1;" : "=f"(y) : "f"(x)); return y;
}
// sigmoid: 1/(1+2^(-x*log2e)); rel err ~1e-7 (proven fastest form on sm_103a)
__device__ __forceinline__ float sigf(float x) {
    return rcpf(1.0f + ex2f(-1.4426950408889634f * x));
}

// R2-proven loop + shape, setup fused per-block. launch_bounds(256,8) pins
// regs to 32 so 8 CTAs/SM fit -> grid 1024 runs as one balanced wave.
__global__ void __launch_bounds__(256, 8) rbf_fused(
    const float* __restrict__ wsp,
    const float4* __restrict__ act,
    const float* __restrict__ dists,
    const float* __restrict__ constants,
    const float* __restrict__ centers,
    const float* __restrict__ radii,
    const float* __restrict__ rotations,
    float4* __restrict__ out,
    float* __restrict__ pen_out,
    int n_pts) {
    __shared__ float4 sp[EC * 3];
    int tid = threadIdx.x;

    // ---- per-block setup: threads 0..63 build packed params in smem ----
    if (tid < EC) {
        int e = tid;
        float rx = fabsf(radii[e * 3 + 0]) + 0.005f;
        float ry = fabsf(radii[e * 3 + 1]) + 0.005f;
        float rz = fabsf(radii[e * 3 + 2]) + 0.005f;
        float d0 = 1.0f / (rx + 1e-8f);
        float d1 = 1.0f / (ry + 1e-8f);
        float d2 = 1.0f / (rz + 1e-8f);

        float a0 = rotations[e * 3 + 0];
        float a1 = rotations[e * 3 + 1];
        float a2 = rotations[e * 3 + 2];
        float cx = cosf(a0), sx = sinf(a0);
        float cy = cosf(a1), sy = sinf(a1);
        float cz = cosf(a2), sz = sinf(a2);

        float R00 = cz * cy, R01 = cz * sy * sx - sz * cx, R02 = cz * sy * cx + sz * sx;
        float R10 = sz * cy, R11 = sz * sy * sx + cz * cx, R12 = sz * sy * cx - cz * sx;
        float R20 = -sy,     R21 = cy * sx,                R22 = cy * cx;

        float c00 = d0 * R00 * R00 + d1 * R01 * R01 + d2 * R02 * R02;
        float c01 = d0 * R00 * R10 + d1 * R01 * R11 + d2 * R02 * R12;
        float c02 = d0 * R00 * R20 + d1 * R01 * R21 + d2 * R02 * R22;
        float c11 = d0 * R10 * R10 + d1 * R11 * R11 + d2 * R12 * R12;
        float c12 = d0 * R10 * R20 + d1 * R11 * R21 + d2 * R12 * R22;
        float c22 = d0 * R20 * R20 + d1 * R21 * R21 + d2 * R22 * R22;

        float ccx = centers[e * 3 + 0];
        float ccy = centers[e * 3 + 1];
        float ccz = centers[e * 3 + 2];
        float cab = fabsf(constants[e]);

        sp[e * 3 + 0] = make_float4(c00, c01, c02, c11);
        sp[e * 3 + 1] = make_float4(c12, c22, ccx, ccy);
        sp[e * 3 + 2] = make_float4(ccz, cab, 0.0f, 0.0f);

        // bbox penalty term, added once (pen_out pre-zeroed by memset node)
        if (blockIdx.x == 0) {
            float p = fmaxf(ccx - 0.6f, 0.0f) + fmaxf(ccy - 0.6f, 0.0f) + fmaxf(ccz - 0.6f, 0.0f)
                    + fmaxf(-0.6f - ccx, 0.0f) + fmaxf(-0.6f - ccy, 0.0f) + fmaxf(-0.35f - ccz, 0.0f);
            if (p != 0.0f) atomicAdd(pen_out, p);
        }
    }
    __syncthreads();

    int n = blockIdx.x * 256 + tid;
    float pen = 0.0f;

    if (n < n_pts) {
        float x = wsp[3 * n + 0];
        float y = wsp[3 * n + 1];
        float z = wsp[3 * n + 2];
        float negl2d = -1.4426950408889634f * dists[n];

        float Ux = 0.0f, Uy = 0.0f, Uz = 0.0f, Uw = 0.0f, S = 0.0f;

        #pragma unroll 8
        for (int e = 0; e < EC; e++) {
            float4 pa = sp[e * 3 + 0];
            float4 pb = sp[e * 3 + 1];
            float4 pc = sp[e * 3 + 2];

            float dx = x - pb.z, dy = y - pb.w, dz = z - pc.x;
            float t0 = pa.x * dx + pa.y * dy + pa.z * dz;
            float t1 = pa.y * dx + pa.w * dy + pb.x * dz;
            float t2 = pa.z * dx + pb.x * dy + pb.y * dz;
            float q  = dx * t0 + dy * t1 + dz * t2;

            // rbf = |c| * exp(-0.5 q) = |c| * 2^(-0.5*log2e*q)  (always > 0)
            float rbf = pc.y * ex2f(-0.7213475204444817f * q);

            pen += fmaxf(rbf - 0.01f, 0.0f);
            S += rbf;

            float4 a = act[(size_t)e * n_pts + n];
            float alpha = 1.0f - ex2f(fmaxf(a.w, 0.0f) * negl2d);
            Ux += rbf * sigf(a.x);
            Uy += rbf * sigf(a.y);
            Uz += rbf * sigf(a.z);
            Uw += rbf * alpha;
        }

        float inv = rcpf(S + 1e-6f);
        out[n] = make_float4(Ux * inv, Uy * inv, Uz * inv, Uw * inv);
    }

    // penalty mean-term reduction: warp shuffle -> smem -> one atomic per block
    #pragma unroll
    for (int o = 16; o; o >>= 1) pen += __shfl_down_sync(0xffffffffu, pen, o);
    __shared__ float wsum[8];
    if ((tid & 31) == 0) wsum[tid >> 5] = pen;
    __syncthreads();
    if (tid == 0) {
        float s = 0.0f;
        #pragma unroll
        for (int i = 0; i < 8; i++) s += wsum[i];
        atomicAdd(pen_out, s * (0.001f / (float)n_pts));
    }
}

extern "C" void kernel_launch(void* const* d_in, const int* in_sizes, int n_in,
                              void* d_out, int out_size) {
    const float* wsp       = (const float*)d_in[0];
    const float* act       = (const float*)d_in[1];
    const float* dists     = (const float*)d_in[2];
    const float* constants = (const float*)d_in[3];
    const float* centers   = (const float*)d_in[4];
    const float* radii     = (const float*)d_in[5];
    const float* rot       = (const float*)d_in[6];

    int n_pts = in_sizes[0] / 3;
    float* out = (float*)d_out;
    float* pen = out + (out_size - 1);

    cudaMemsetAsync(pen, 0, sizeof(float));

    int blocks = (n_pts + 255) / 256;
    rbf_fused<<<blocks, 256>>>(wsp, (const float4*)act, dists,
                               constants, centers, radii, rot,
                               (float4*)out, pen, n_pts);
}